// round 4
// baseline (speedup 1.0000x reference)
#include <cuda_runtime.h>

#define N_NODES 20000
#define N_IN    512
#define N_OUT   512

// 41 MB scratch for agg = segment_sum(vals * x[col])  (static: no runtime alloc)
__device__ float g_agg[(size_t)N_NODES * N_IN];

// ---------------------------------------------------------------------------
// Kernel 1: zero the aggregation scratch (vectorized grid-stride)
// ---------------------------------------------------------------------------
__global__ void zero_agg_kernel() {
    const int n4 = (N_NODES * N_IN) / 4;
    float4 z = make_float4(0.f, 0.f, 0.f, 0.f);
    float4* p = reinterpret_cast<float4*>(g_agg);
    for (int i = blockIdx.x * blockDim.x + threadIdx.x; i < n4;
         i += gridDim.x * blockDim.x) {
        p[i] = z;
    }
}

// ---------------------------------------------------------------------------
// Kernel 2: edge scatter.  4 edges per 512-thread block; 128 threads per edge,
// each thread handles one float4 of the 512-wide feature row.
// agg[row[e]] += vals[e] * x[col[e]]
// ---------------------------------------------------------------------------
__global__ __launch_bounds__(512) void scatter_kernel(
    const float* __restrict__ x,
    const float* __restrict__ vals,
    const int*   __restrict__ row,
    const int*   __restrict__ col,
    int E)
{
    int t = threadIdx.x;
    int e = blockIdx.x * 4 + (t >> 7);
    if (e >= E) return;
    int f4 = t & 127;                      // float4 lane within the 512-feature row

    float v = vals[e];                     // broadcast loads (all 128 threads same addr)
    int   c = col[e];
    int   r = row[e];

    float4 xv = reinterpret_cast<const float4*>(x + (size_t)c * N_IN)[f4];
    float* dst = g_agg + (size_t)r * N_IN + f4 * 4;
    atomicAdd(dst + 0, v * xv.x);
    atomicAdd(dst + 1, v * xv.y);
    atomicAdd(dst + 2, v * xv.z);
    atomicAdd(dst + 3, v * xv.w);
}

// ---------------------------------------------------------------------------
// Kernel 3: out = agg @ W^T   (C[m][n] = sum_k A[m][k] * W[n][k])
// Both A and W are K-contiguous row-major -> vectorized global loads,
// transposed into smem as [BK][BM] / [BK][BN].
// 128x128 tile, BK=16, 256 threads, 8x8 microtile per thread.
// ---------------------------------------------------------------------------
#define BM 128
#define BN 128
#define BK 16
#define TM 8
#define TN 8

__global__ __launch_bounds__(256) void gemm_kernel(
    const float* __restrict__ W,
    float* __restrict__ out)
{
    __shared__ float As[BK][BM];
    __shared__ float Bs[BK][BN];

    const int m0  = blockIdx.y * BM;
    const int n0  = blockIdx.x * BN;
    const int tid = threadIdx.x;
    const int tr  = tid >> 4;   // 0..15
    const int tc  = tid & 15;   // 0..15

    // Global-load mapping: 128 rows x 4 float4 per row = 512 float4 loads,
    // 256 threads -> 2 each.
    const int lr = tid >> 2;    // 0..63
    const int lc = tid & 3;     // 0..3 (which float4 in the 16-wide K slice)

    float acc[TM][TN];
    #pragma unroll
    for (int i = 0; i < TM; i++)
        #pragma unroll
        for (int j = 0; j < TN; j++) acc[i][j] = 0.f;

    for (int kt = 0; kt < N_IN; kt += BK) {
        // Load A tile (agg), transposed into As[k][m]
        #pragma unroll
        for (int i = 0; i < 2; i++) {
            int r  = lr + i * 64;
            int gm = m0 + r;
            float4 a = make_float4(0.f, 0.f, 0.f, 0.f);
            if (gm < N_NODES)
                a = reinterpret_cast<const float4*>(
                        g_agg + (size_t)gm * N_IN + kt)[lc];
            As[lc * 4 + 0][r] = a.x;
            As[lc * 4 + 1][r] = a.y;
            As[lc * 4 + 2][r] = a.z;
            As[lc * 4 + 3][r] = a.w;
        }
        // Load W tile, transposed into Bs[k][n]  (N_OUT=512 exact, no guard)
        #pragma unroll
        for (int i = 0; i < 2; i++) {
            int r = lr + i * 64;
            float4 b = reinterpret_cast<const float4*>(
                           W + (size_t)(n0 + r) * N_IN + kt)[lc];
            Bs[lc * 4 + 0][r] = b.x;
            Bs[lc * 4 + 1][r] = b.y;
            Bs[lc * 4 + 2][r] = b.z;
            Bs[lc * 4 + 3][r] = b.w;
        }
        __syncthreads();

        #pragma unroll
        for (int kk = 0; kk < BK; kk++) {
            float ra[TM], rb[TN];
            #pragma unroll
            for (int i = 0; i < TM; i++) ra[i] = As[kk][tr * TM + i];
            #pragma unroll
            for (int j = 0; j < TN; j++) rb[j] = Bs[kk][tc * TN + j];
            #pragma unroll
            for (int i = 0; i < TM; i++)
                #pragma unroll
                for (int j = 0; j < TN; j++)
                    acc[i][j] += ra[i] * rb[j];
        }
        __syncthreads();
    }

    // Store 8x8 microtile (vectorized, row-guarded)
    #pragma unroll
    for (int i = 0; i < TM; i++) {
        int gm = m0 + tr * TM + i;
        if (gm < N_NODES) {
            float4* op = reinterpret_cast<float4*>(
                out + (size_t)gm * N_OUT + n0 + tc * TN);
            op[0] = make_float4(acc[i][0], acc[i][1], acc[i][2], acc[i][3]);
            op[1] = make_float4(acc[i][4], acc[i][5], acc[i][6], acc[i][7]);
        }
    }
}

// ---------------------------------------------------------------------------
// Launch
// ---------------------------------------------------------------------------
extern "C" void kernel_launch(void* const* d_in, const int* in_sizes, int n_in,
                              void* d_out, int out_size)
{
    const float* x    = (const float*)d_in[0];
    const float* vals = (const float*)d_in[1];
    const float* W    = (const float*)d_in[2];
    const int*   row  = (const int*)d_in[3];
    const int*   col  = (const int*)d_in[4];
    float*       out  = (float*)d_out;

    int E = in_sizes[1];   // n_edges (vals element count)

    zero_agg_kernel<<<1024, 256>>>();
    scatter_kernel<<<(E + 3) / 4, 512>>>(x, vals, row, col, E);

    dim3 grid(N_OUT / BN, (N_NODES + BM - 1) / BM);   // (4, 157)
    gemm_kernel<<<grid, 256>>>(W, out);
}

// round 8
// speedup vs baseline: 1.8512x; 1.8512x over previous
#include <cuda_runtime.h>
#include <cuda_bf16.h>
#include <cstdint>

#define N_NODES 20000
#define N_IN    512
#define N_OUT   512
#define M_PAD   20096            // 157 * 128, padded so GEMM A-loads need no guard

// Static device scratch (no runtime allocation)
__device__ float          g_agg[(size_t)N_NODES * N_IN];          // 41 MB
__device__ __nv_bfloat16  g_Ahi[(size_t)M_PAD * N_IN];            // 20.6 MB
__device__ __nv_bfloat16  g_Alo[(size_t)M_PAD * N_IN];            // 20.6 MB
__device__ __nv_bfloat16  g_Whi[(size_t)N_OUT * N_IN];            // 0.5 MB
__device__ __nv_bfloat16  g_Wlo[(size_t)N_OUT * N_IN];            // 0.5 MB

// ---------------------------------------------------------------------------
// Helpers
// ---------------------------------------------------------------------------
__device__ __forceinline__ uint32_t smem_u32(const void* p) {
    uint32_t a;
    asm("{ .reg .u64 t; cvta.to.shared.u64 t, %1; cvt.u32.u64 %0, t; }"
        : "=r"(a) : "l"(p));
    return a;
}

// Split 4 fp32 into bf16 hi (rn) and bf16 lo = bf16(a - float(hi)); packed pairs
__device__ __forceinline__ void split4(float4 f, uint32_t& hi0, uint32_t& hi1,
                                       uint32_t& lo0, uint32_t& lo1) {
    __nv_bfloat16 hx = __float2bfloat16(f.x);
    __nv_bfloat16 hy = __float2bfloat16(f.y);
    __nv_bfloat16 hz = __float2bfloat16(f.z);
    __nv_bfloat16 hw = __float2bfloat16(f.w);
    __nv_bfloat16 lx = __float2bfloat16(f.x - __bfloat162float(hx));
    __nv_bfloat16 ly = __float2bfloat16(f.y - __bfloat162float(hy));
    __nv_bfloat16 lz = __float2bfloat16(f.z - __bfloat162float(hz));
    __nv_bfloat16 lw = __float2bfloat16(f.w - __bfloat162float(hw));
    __nv_bfloat162 H0 = __halves2bfloat162(hx, hy);
    __nv_bfloat162 H1 = __halves2bfloat162(hz, hw);
    __nv_bfloat162 L0 = __halves2bfloat162(lx, ly);
    __nv_bfloat162 L1 = __halves2bfloat162(lz, lw);
    hi0 = *reinterpret_cast<uint32_t*>(&H0);
    hi1 = *reinterpret_cast<uint32_t*>(&H1);
    lo0 = *reinterpret_cast<uint32_t*>(&L0);
    lo1 = *reinterpret_cast<uint32_t*>(&L1);
}

__device__ __forceinline__ void cp_async16(uint32_t smem_addr, const void* gptr) {
    asm volatile("cp.async.cg.shared.global [%0], [%1], 16;"
                 :: "r"(smem_addr), "l"(gptr) : "memory");
}

__device__ __forceinline__ void ldsm_x4(uint32_t& r0, uint32_t& r1,
                                        uint32_t& r2, uint32_t& r3, uint32_t addr) {
    asm volatile("ldmatrix.sync.aligned.m8n8.x4.shared.b16 {%0,%1,%2,%3}, [%4];"
                 : "=r"(r0), "=r"(r1), "=r"(r2), "=r"(r3) : "r"(addr));
}

__device__ __forceinline__ void mma_bf16(float& c0, float& c1, float& c2, float& c3,
                                         uint32_t a0, uint32_t a1, uint32_t a2, uint32_t a3,
                                         uint32_t b0, uint32_t b1) {
    asm volatile(
        "mma.sync.aligned.m16n8k16.row.col.f32.bf16.bf16.f32 "
        "{%0,%1,%2,%3}, {%4,%5,%6,%7}, {%8,%9}, {%0,%1,%2,%3};"
        : "+f"(c0), "+f"(c1), "+f"(c2), "+f"(c3)
        : "r"(a0), "r"(a1), "r"(a2), "r"(a3), "r"(b0), "r"(b1));
}

__device__ __forceinline__ uint32_t sw128(uint32_t off) {
    return off ^ ((off >> 3) & 0x70);
}

// ---------------------------------------------------------------------------
// Kernel 1: zero the aggregation scratch
// ---------------------------------------------------------------------------
__global__ void zero_agg_kernel() {
    const int n4 = (N_NODES * N_IN) / 4;
    float4 z = make_float4(0.f, 0.f, 0.f, 0.f);
    float4* p = reinterpret_cast<float4*>(g_agg);
    for (int i = blockIdx.x * blockDim.x + threadIdx.x; i < n4;
         i += gridDim.x * blockDim.x) {
        p[i] = z;
    }
}

// ---------------------------------------------------------------------------
// Kernel 2: edge scatter with vector reduction (red.global.add.v4.f32)
// 4 edges per 512-thread block; 128 threads per edge (one float4 each).
// ---------------------------------------------------------------------------
__global__ __launch_bounds__(512) void scatter_kernel(
    const float* __restrict__ x,
    const float* __restrict__ vals,
    const int*   __restrict__ row,
    const int*   __restrict__ col,
    int E)
{
    int t = threadIdx.x;
    int e = blockIdx.x * 4 + (t >> 7);
    if (e >= E) return;
    int f4 = t & 127;

    float v = vals[e];
    int   c = col[e];
    int   r = row[e];

    float4 xv = reinterpret_cast<const float4*>(x + (size_t)c * N_IN)[f4];
    float* dst = g_agg + (size_t)r * N_IN + f4 * 4;
    asm volatile("red.global.add.v4.f32 [%0], {%1, %2, %3, %4};"
                 :: "l"(dst), "f"(v * xv.x), "f"(v * xv.y),
                    "f"(v * xv.z), "f"(v * xv.w)
                 : "memory");
}

// ---------------------------------------------------------------------------
// Kernel 3a/3b: split fp32 -> bf16 hi/lo global arrays (A padded to M_PAD rows)
// ---------------------------------------------------------------------------
__global__ void split_a_kernel() {
    const int n4 = (M_PAD * N_IN) / 4;
    uint32_t* hi = reinterpret_cast<uint32_t*>(g_Ahi);
    uint32_t* lo = reinterpret_cast<uint32_t*>(g_Alo);
    const float4* src = reinterpret_cast<const float4*>(g_agg);
    const int n4_real = (N_NODES * N_IN) / 4;
    for (int i = blockIdx.x * blockDim.x + threadIdx.x; i < n4;
         i += gridDim.x * blockDim.x) {
        float4 f = (i < n4_real) ? src[i] : make_float4(0.f, 0.f, 0.f, 0.f);
        uint32_t h0, h1, l0, l1;
        split4(f, h0, h1, l0, l1);
        hi[i * 2] = h0; hi[i * 2 + 1] = h1;
        lo[i * 2] = l0; lo[i * 2 + 1] = l1;
    }
}

__global__ void split_w_kernel(const float* __restrict__ W) {
    const int n4 = (N_OUT * N_IN) / 4;
    uint32_t* hi = reinterpret_cast<uint32_t*>(g_Whi);
    uint32_t* lo = reinterpret_cast<uint32_t*>(g_Wlo);
    const float4* src = reinterpret_cast<const float4*>(W);
    for (int i = blockIdx.x * blockDim.x + threadIdx.x; i < n4;
         i += gridDim.x * blockDim.x) {
        uint32_t h0, h1, l0, l1;
        split4(src[i], h0, h1, l0, l1);
        hi[i * 2] = h0; hi[i * 2 + 1] = h1;
        lo[i * 2] = l0; lo[i * 2 + 1] = l1;
    }
}

// ---------------------------------------------------------------------------
// Kernel 4: out = agg @ W^T via mma.sync bf16x3 (hi/lo split, fp32 accum)
// Block tile 128x128, BK=64 bf16; 8 warps as 2(m) x 4(n), warp tile 64x32.
// cp.async 16B loads into SW128-swizzled smem; conflict-free ldmatrix.
// ---------------------------------------------------------------------------
#define GBM 128
#define GBN 128
#define NCHUNK (N_IN / 64)     // 8

#define OFF_AHI 0
#define OFF_ALO 16384
#define OFF_BHI 32768
#define OFF_BLO 49152
#define GEMM_SMEM 65536

__global__ __launch_bounds__(256, 2) void mma_gemm_kernel(float* __restrict__ out)
{
    extern __shared__ __align__(1024) char smem[];
    const uint32_t sbase = smem_u32(smem);
    const int tid = threadIdx.x;
    const int wid = tid >> 5;
    const int lane = tid & 31;
    const int wm = wid >> 2;            // 0..1 : rows wm*64
    const int wn = wid & 3;             // 0..3 : cols wn*32
    const int m0 = blockIdx.y * GBM;
    const int n0 = blockIdx.x * GBN;

    // cp.async source bases for this thread: row r, half h (which 64B of the 128B row)
    const int r = tid >> 1;             // 0..127
    const int h = tid & 1;              // 0..1
    const char* srcA_hi = (const char*)(g_Ahi + (size_t)(m0 + r) * N_IN);
    const char* srcA_lo = (const char*)(g_Alo + (size_t)(m0 + r) * N_IN);
    const char* srcB_hi = (const char*)(g_Whi + (size_t)(n0 + r) * N_IN);
    const char* srcB_lo = (const char*)(g_Wlo + (size_t)(n0 + r) * N_IN);

    float acc[4][4][4];
    #pragma unroll
    for (int i = 0; i < 4; i++)
        #pragma unroll
        for (int j = 0; j < 4; j++)
            #pragma unroll
            for (int k = 0; k < 4; k++) acc[i][j][k] = 0.f;

    const uint32_t aOff[3] = {OFF_AHI, OFF_ALO, OFF_AHI};
    const uint32_t bOff[3] = {OFF_BHI, OFF_BHI, OFF_BLO};

    for (int chunk = 0; chunk < NCHUNK; chunk++) {
        // ---- load 4 tiles (128 rows x 128B each) via cp.async ----
        {
            const int cbyte = chunk * 128;   // 64 bf16 = 128 bytes per row per chunk
            #pragma unroll
            for (int jj = 0; jj < 4; jj++) {
                const int j = h * 4 + jj;                      // 16B chunk 0..7
                const uint32_t dst = sw128((uint32_t)(r * 128 + j * 16));
                const int so = cbyte + j * 16;
                cp_async16(sbase + OFF_AHI + dst, srcA_hi + so);
                cp_async16(sbase + OFF_ALO + dst, srcA_lo + so);
                cp_async16(sbase + OFF_BHI + dst, srcB_hi + so);
                cp_async16(sbase + OFF_BLO + dst, srcB_lo + so);
            }
            asm volatile("cp.async.commit_group;" ::: "memory");
            asm volatile("cp.async.wait_group 0;" ::: "memory");
        }
        __syncthreads();

        // ---- compute: 3 chains x 4 k16-steps ----
        #pragma unroll
        for (int c = 0; c < 3; c++) {
            const uint32_t aB = sbase + aOff[c];
            const uint32_t bB = sbase + bOff[c];
            #pragma unroll
            for (int ks = 0; ks < 4; ks++) {
                // A fragments: 4 m16 groups
                uint32_t a[4][4];
                #pragma unroll
                for (int mf = 0; mf < 4; mf++) {
                    uint32_t off = (uint32_t)((wm * 64 + mf * 16 +
                                   ((lane >> 3) & 1) * 8 + (lane & 7)) * 128
                                   + ks * 32 + (lane >> 4) * 16);
                    ldsm_x4(a[mf][0], a[mf][1], a[mf][2], a[mf][3], aB + sw128(off));
                }
                // B fragments: 4 n8 groups (2 x4 loads)
                uint32_t b[4][2];
                #pragma unroll
                for (int nf2 = 0; nf2 < 2; nf2++) {
                    uint32_t off = (uint32_t)((wn * 32 + nf2 * 16 +
                                   ((lane >> 4) & 1) * 8 + (lane & 7)) * 128
                                   + ks * 32 + ((lane >> 3) & 1) * 16);
                    ldsm_x4(b[nf2 * 2][0], b[nf2 * 2][1],
                            b[nf2 * 2 + 1][0], b[nf2 * 2 + 1][1], bB + sw128(off));
                }
                #pragma unroll
                for (int mf = 0; mf < 4; mf++)
                    #pragma unroll
                    for (int nf = 0; nf < 4; nf++)
                        mma_bf16(acc[mf][nf][0], acc[mf][nf][1],
                                 acc[mf][nf][2], acc[mf][nf][3],
                                 a[mf][0], a[mf][1], a[mf][2], a[mf][3],
                                 b[nf][0], b[nf][1]);
            }
        }
        __syncthreads();
    }

    // ---- epilogue: c0,c1 at (m, n..n+1); c2,c3 at (m+8, n..n+1) ----
    #pragma unroll
    for (int mf = 0; mf < 4; mf++) {
        const int mrow = m0 + wm * 64 + mf * 16 + (lane >> 2);
        #pragma unroll
        for (int nf = 0; nf < 4; nf++) {
            const int ncol = n0 + wn * 32 + nf * 8 + (lane & 3) * 2;
            if (mrow < N_NODES) {
                float2* p = reinterpret_cast<float2*>(out + (size_t)mrow * N_OUT + ncol);
                *p = make_float2(acc[mf][nf][0], acc[mf][nf][1]);
            }
            if (mrow + 8 < N_NODES) {
                float2* p = reinterpret_cast<float2*>(out + (size_t)(mrow + 8) * N_OUT + ncol);
                *p = make_float2(acc[mf][nf][2], acc[mf][nf][3]);
            }
        }
    }
}

// ---------------------------------------------------------------------------
// Launch
// ---------------------------------------------------------------------------
extern "C" void kernel_launch(void* const* d_in, const int* in_sizes, int n_in,
                              void* d_out, int out_size)
{
    const float* x    = (const float*)d_in[0];
    const float* vals = (const float*)d_in[1];
    const float* W    = (const float*)d_in[2];
    const int*   row  = (const int*)d_in[3];
    const int*   col  = (const int*)d_in[4];
    float*       out  = (float*)d_out;

    int E = in_sizes[1];

    static bool s_init = false;
    if (!s_init) {
        cudaFuncSetAttribute(mma_gemm_kernel,
                             cudaFuncAttributeMaxDynamicSharedMemorySize, GEMM_SMEM);
        s_init = true;
    }

    zero_agg_kernel<<<1024, 256>>>();
    scatter_kernel<<<(E + 3) / 4, 512>>>(x, vals, row, col, E);
    split_a_kernel<<<2048, 256>>>();
    split_w_kernel<<<256, 256>>>(W);

    dim3 grid(N_OUT / GBN, M_PAD / GBM);   // (4, 157)
    mma_gemm_kernel<<<grid, 256, GEMM_SMEM>>>(out);
}

// round 10
// speedup vs baseline: 2.7174x; 1.4679x over previous
#include <cuda_runtime.h>
#include <cuda_bf16.h>
#include <cstdint>

#define N_NODES 20000
#define N_EDGES 160000
#define N_IN    512
#define N_OUT   512
#define M_PAD   20096            // 157 * 128

// Static device scratch (no runtime allocation; zero-initialized at load)
__device__ __nv_bfloat16  g_Ahi[(size_t)M_PAD * N_IN];   // 20.6 MB (padding rows stay 0)
__device__ __nv_bfloat16  g_Alo[(size_t)M_PAD * N_IN];   // 20.6 MB
__device__ __nv_bfloat16  g_Whi[(size_t)N_OUT * N_IN];
__device__ __nv_bfloat16  g_Wlo[(size_t)N_OUT * N_IN];
__device__ int            g_cnt[N_NODES];                // histogram, then fill cursor
__device__ int            g_ofs[N_NODES + 1];            // CSR row offsets
__device__ int            g_csr_col[N_EDGES];
__device__ float          g_csr_val[N_EDGES];

// ---------------------------------------------------------------------------
// Helpers
// ---------------------------------------------------------------------------
__device__ __forceinline__ uint32_t smem_u32(const void* p) {
    uint32_t a;
    asm("{ .reg .u64 t; cvta.to.shared.u64 t, %1; cvt.u32.u64 %0, t; }"
        : "=r"(a) : "l"(p));
    return a;
}

// Split 4 fp32 into bf16 hi (rn) and bf16 lo = bf16(a - float(hi)); packed pairs
__device__ __forceinline__ void split4(float4 f, uint32_t& hi0, uint32_t& hi1,
                                       uint32_t& lo0, uint32_t& lo1) {
    __nv_bfloat16 hx = __float2bfloat16(f.x);
    __nv_bfloat16 hy = __float2bfloat16(f.y);
    __nv_bfloat16 hz = __float2bfloat16(f.z);
    __nv_bfloat16 hw = __float2bfloat16(f.w);
    __nv_bfloat16 lx = __float2bfloat16(f.x - __bfloat162float(hx));
    __nv_bfloat16 ly = __float2bfloat16(f.y - __bfloat162float(hy));
    __nv_bfloat16 lz = __float2bfloat16(f.z - __bfloat162float(hz));
    __nv_bfloat16 lw = __float2bfloat16(f.w - __bfloat162float(hw));
    __nv_bfloat162 H0 = __halves2bfloat162(hx, hy);
    __nv_bfloat162 H1 = __halves2bfloat162(hz, hw);
    __nv_bfloat162 L0 = __halves2bfloat162(lx, ly);
    __nv_bfloat162 L1 = __halves2bfloat162(lz, lw);
    hi0 = *reinterpret_cast<uint32_t*>(&H0);
    hi1 = *reinterpret_cast<uint32_t*>(&H1);
    lo0 = *reinterpret_cast<uint32_t*>(&L0);
    lo1 = *reinterpret_cast<uint32_t*>(&L1);
}

__device__ __forceinline__ void cp_async16(uint32_t smem_addr, const void* gptr) {
    asm volatile("cp.async.cg.shared.global [%0], [%1], 16;"
                 :: "r"(smem_addr), "l"(gptr) : "memory");
}

__device__ __forceinline__ void ldsm_x4(uint32_t& r0, uint32_t& r1,
                                        uint32_t& r2, uint32_t& r3, uint32_t addr) {
    asm volatile("ldmatrix.sync.aligned.m8n8.x4.shared.b16 {%0,%1,%2,%3}, [%4];"
                 : "=r"(r0), "=r"(r1), "=r"(r2), "=r"(r3) : "r"(addr));
}

__device__ __forceinline__ void mma_bf16(float& c0, float& c1, float& c2, float& c3,
                                         uint32_t a0, uint32_t a1, uint32_t a2, uint32_t a3,
                                         uint32_t b0, uint32_t b1) {
    asm volatile(
        "mma.sync.aligned.m16n8k16.row.col.f32.bf16.bf16.f32 "
        "{%0,%1,%2,%3}, {%4,%5,%6,%7}, {%8,%9}, {%0,%1,%2,%3};"
        : "+f"(c0), "+f"(c1), "+f"(c2), "+f"(c3)
        : "r"(a0), "r"(a1), "r"(a2), "r"(a3), "r"(b0), "r"(b1));
}

__device__ __forceinline__ uint32_t sw128(uint32_t off) {
    return off ^ ((off >> 3) & 0x70);
}

// ---------------------------------------------------------------------------
// CSR build: zero counts -> histogram -> scan -> fill
// ---------------------------------------------------------------------------
__global__ void zero_cnt_kernel() {
    int i = blockIdx.x * blockDim.x + threadIdx.x;
    if (i < N_NODES) g_cnt[i] = 0;
}

__global__ void hist_kernel(const int* __restrict__ row, int E) {
    int e = blockIdx.x * blockDim.x + threadIdx.x;
    if (e < E) atomicAdd(&g_cnt[row[e]], 1);
}

// Single-block exclusive scan of g_cnt -> g_ofs; re-init g_cnt as fill cursor.
__global__ __launch_bounds__(1024) void scan_kernel() {
    __shared__ int s[1024];
    const int t = threadIdx.x;
    const int PER = 20;                        // 1024*20 = 20480 >= N_NODES
    const int beg = t * PER;
    const int end = min(beg + PER, N_NODES);

    int part = 0;
    for (int i = beg; i < end; i++) part += g_cnt[i];
    s[t] = part;
    __syncthreads();
    for (int off = 1; off < 1024; off <<= 1) {
        int v = (t >= off) ? s[t - off] : 0;
        __syncthreads();
        s[t] += v;
        __syncthreads();
    }
    int base = s[t] - part;                    // exclusive prefix
    for (int i = beg; i < end; i++) {
        int c = g_cnt[i];
        g_ofs[i] = base;
        g_cnt[i] = base;                       // cursor for fill
        base += c;
    }
    if (t == 1023) g_ofs[N_NODES] = base;      // == E (tail parts are 0)
}

__global__ void fill_kernel(const float* __restrict__ vals,
                            const int* __restrict__ row,
                            const int* __restrict__ col, int E) {
    int e = blockIdx.x * blockDim.x + threadIdx.x;
    if (e < E) {
        int p = atomicAdd(&g_cnt[row[e]], 1);
        g_csr_col[p] = col[e];
        g_csr_val[p] = vals[e];
    }
}

// ---------------------------------------------------------------------------
// Gather + bf16 split: one node per 128 threads (4 nodes / 512-thread block).
// acc[f4] = sum_e val_e * x[col_e][f4]; write bf16 hi/lo rows directly.
// ---------------------------------------------------------------------------
__global__ __launch_bounds__(512) void gather_split_kernel(const float* __restrict__ x)
{
    const int node = blockIdx.x * 4 + (threadIdx.x >> 7);
    if (node >= N_NODES) return;
    const int f4 = threadIdx.x & 127;

    const int beg = g_ofs[node];
    const int end = g_ofs[node + 1];

    float4 acc = make_float4(0.f, 0.f, 0.f, 0.f);
    for (int p = beg; p < end; p++) {
        const int   c = g_csr_col[p];          // warp-uniform (broadcast)
        const float v = g_csr_val[p];
        float4 xv = reinterpret_cast<const float4*>(x + (size_t)c * N_IN)[f4];
        acc.x += v * xv.x; acc.y += v * xv.y;
        acc.z += v * xv.z; acc.w += v * xv.w;
    }

    uint32_t h0, h1, l0, l1;
    split4(acc, h0, h1, l0, l1);
    uint2* hp = reinterpret_cast<uint2*>(g_Ahi + (size_t)node * N_IN) + f4;
    uint2* lp = reinterpret_cast<uint2*>(g_Alo + (size_t)node * N_IN) + f4;
    *hp = make_uint2(h0, h1);
    *lp = make_uint2(l0, l1);
}

// ---------------------------------------------------------------------------
// W split
// ---------------------------------------------------------------------------
__global__ void split_w_kernel(const float* __restrict__ W) {
    const int n4 = (N_OUT * N_IN) / 4;
    uint32_t* hi = reinterpret_cast<uint32_t*>(g_Whi);
    uint32_t* lo = reinterpret_cast<uint32_t*>(g_Wlo);
    const float4* src = reinterpret_cast<const float4*>(W);
    for (int i = blockIdx.x * blockDim.x + threadIdx.x; i < n4;
         i += gridDim.x * blockDim.x) {
        uint32_t h0, h1, l0, l1;
        split4(src[i], h0, h1, l0, l1);
        hi[i * 2] = h0; hi[i * 2 + 1] = h1;
        lo[i * 2] = l0; lo[i * 2 + 1] = l1;
    }
}

// ---------------------------------------------------------------------------
// GEMM: out = agg @ W^T via mma.sync bf16x3 (hi/lo split, fp32 accum)
// Block tile 128x128, BK=64; 8 warps (2m x 4n), warp tile 64x32.
// Chain order per ks: hi*hi -> hi*lo (reuse A regs) -> lo*hi (reuse Bhi regs):
// 12 ldsm.x4 per ks instead of 18.
// ---------------------------------------------------------------------------
#define GBM 128
#define GBN 128
#define NCHUNK (N_IN / 64)     // 8

#define OFF_AHI 0
#define OFF_ALO 16384
#define OFF_BHI 32768
#define OFF_BLO 49152
#define GEMM_SMEM 65536

__global__ __launch_bounds__(256, 2) void mma_gemm_kernel(float* __restrict__ out)
{
    extern __shared__ __align__(1024) char smem[];
    const uint32_t sbase = smem_u32(smem);
    const int tid = threadIdx.x;
    const int wid = tid >> 5;
    const int lane = tid & 31;
    const int wm = wid >> 2;            // 0..1 : rows wm*64
    const int wn = wid & 3;             // 0..3 : cols wn*32
    const int m0 = blockIdx.y * GBM;
    const int n0 = blockIdx.x * GBN;

    const int r = tid >> 1;             // 0..127
    const int h = tid & 1;              // 0..1
    const char* srcA_hi = (const char*)(g_Ahi + (size_t)(m0 + r) * N_IN);
    const char* srcA_lo = (const char*)(g_Alo + (size_t)(m0 + r) * N_IN);
    const char* srcB_hi = (const char*)(g_Whi + (size_t)(n0 + r) * N_IN);
    const char* srcB_lo = (const char*)(g_Wlo + (size_t)(n0 + r) * N_IN);

    float acc[4][4][4];
    #pragma unroll
    for (int i = 0; i < 4; i++)
        #pragma unroll
        for (int j = 0; j < 4; j++)
            #pragma unroll
            for (int k = 0; k < 4; k++) acc[i][j][k] = 0.f;

    for (int chunk = 0; chunk < NCHUNK; chunk++) {
        // ---- load 4 tiles (128 rows x 128B each) via cp.async ----
        {
            const int cbyte = chunk * 128;
            #pragma unroll
            for (int jj = 0; jj < 4; jj++) {
                const int j = h * 4 + jj;
                const uint32_t dst = sw128((uint32_t)(r * 128 + j * 16));
                const int so = cbyte + j * 16;
                cp_async16(sbase + OFF_AHI + dst, srcA_hi + so);
                cp_async16(sbase + OFF_ALO + dst, srcA_lo + so);
                cp_async16(sbase + OFF_BHI + dst, srcB_hi + so);
                cp_async16(sbase + OFF_BLO + dst, srcB_lo + so);
            }
            asm volatile("cp.async.commit_group;" ::: "memory");
            asm volatile("cp.async.wait_group 0;" ::: "memory");
        }
        __syncthreads();

        #pragma unroll
        for (int ks = 0; ks < 4; ks++) {
            uint32_t a[4][4], bh[4][2], bl[4][2];

            // A-hi fragments
            #pragma unroll
            for (int mf = 0; mf < 4; mf++) {
                uint32_t off = (uint32_t)((wm * 64 + mf * 16 +
                               ((lane >> 3) & 1) * 8 + (lane & 7)) * 128
                               + ks * 32 + (lane >> 4) * 16);
                ldsm_x4(a[mf][0], a[mf][1], a[mf][2], a[mf][3],
                        sbase + OFF_AHI + sw128(off));
            }
            // B-hi fragments
            #pragma unroll
            for (int nf2 = 0; nf2 < 2; nf2++) {
                uint32_t off = (uint32_t)((wn * 32 + nf2 * 16 +
                               ((lane >> 4) & 1) * 8 + (lane & 7)) * 128
                               + ks * 32 + ((lane >> 3) & 1) * 16);
                ldsm_x4(bh[nf2 * 2][0], bh[nf2 * 2][1],
                        bh[nf2 * 2 + 1][0], bh[nf2 * 2 + 1][1],
                        sbase + OFF_BHI + sw128(off));
            }
            // chain 1: hi * hi
            #pragma unroll
            for (int mf = 0; mf < 4; mf++)
                #pragma unroll
                for (int nf = 0; nf < 4; nf++)
                    mma_bf16(acc[mf][nf][0], acc[mf][nf][1],
                             acc[mf][nf][2], acc[mf][nf][3],
                             a[mf][0], a[mf][1], a[mf][2], a[mf][3],
                             bh[nf][0], bh[nf][1]);

            // B-lo fragments
            #pragma unroll
            for (int nf2 = 0; nf2 < 2; nf2++) {
                uint32_t off = (uint32_t)((wn * 32 + nf2 * 16 +
                               ((lane >> 4) & 1) * 8 + (lane & 7)) * 128
                               + ks * 32 + ((lane >> 3) & 1) * 16);
                ldsm_x4(bl[nf2 * 2][0], bl[nf2 * 2][1],
                        bl[nf2 * 2 + 1][0], bl[nf2 * 2 + 1][1],
                        sbase + OFF_BLO + sw128(off));
            }
            // chain 2: hi * lo  (reuse A-hi regs)
            #pragma unroll
            for (int mf = 0; mf < 4; mf++)
                #pragma unroll
                for (int nf = 0; nf < 4; nf++)
                    mma_bf16(acc[mf][nf][0], acc[mf][nf][1],
                             acc[mf][nf][2], acc[mf][nf][3],
                             a[mf][0], a[mf][1], a[mf][2], a[mf][3],
                             bl[nf][0], bl[nf][1]);

            // A-lo fragments (overwrite a)
            #pragma unroll
            for (int mf = 0; mf < 4; mf++) {
                uint32_t off = (uint32_t)((wm * 64 + mf * 16 +
                               ((lane >> 3) & 1) * 8 + (lane & 7)) * 128
                               + ks * 32 + (lane >> 4) * 16);
                ldsm_x4(a[mf][0], a[mf][1], a[mf][2], a[mf][3],
                        sbase + OFF_ALO + sw128(off));
            }
            // chain 3: lo * hi  (reuse B-hi regs)
            #pragma unroll
            for (int mf = 0; mf < 4; mf++)
                #pragma unroll
                for (int nf = 0; nf < 4; nf++)
                    mma_bf16(acc[mf][nf][0], acc[mf][nf][1],
                             acc[mf][nf][2], acc[mf][nf][3],
                             a[mf][0], a[mf][1], a[mf][2], a[mf][3],
                             bh[nf][0], bh[nf][1]);
        }
        __syncthreads();
    }

    // ---- epilogue ----
    #pragma unroll
    for (int mf = 0; mf < 4; mf++) {
        const int mrow = m0 + wm * 64 + mf * 16 + (lane >> 2);
        #pragma unroll
        for (int nf = 0; nf < 4; nf++) {
            const int ncol = n0 + wn * 32 + nf * 8 + (lane & 3) * 2;
            if (mrow < N_NODES) {
                float2* p = reinterpret_cast<float2*>(out + (size_t)mrow * N_OUT + ncol);
                *p = make_float2(acc[mf][nf][0], acc[mf][nf][1]);
            }
            if (mrow + 8 < N_NODES) {
                float2* p = reinterpret_cast<float2*>(out + (size_t)(mrow + 8) * N_OUT + ncol);
                *p = make_float2(acc[mf][nf][2], acc[mf][nf][3]);
            }
        }
    }
}

// ---------------------------------------------------------------------------
// Launch
// ---------------------------------------------------------------------------
extern "C" void kernel_launch(void* const* d_in, const int* in_sizes, int n_in,
                              void* d_out, int out_size)
{
    const float* x    = (const float*)d_in[0];
    const float* vals = (const float*)d_in[1];
    const float* W    = (const float*)d_in[2];
    const int*   row  = (const int*)d_in[3];
    const int*   col  = (const int*)d_in[4];
    float*       out  = (float*)d_out;

    int E = in_sizes[1];

    static bool s_init = false;
    if (!s_init) {
        cudaFuncSetAttribute(mma_gemm_kernel,
                             cudaFuncAttributeMaxDynamicSharedMemorySize, GEMM_SMEM);
        s_init = true;
    }

    zero_cnt_kernel<<<(N_NODES + 511) / 512, 512>>>();
    hist_kernel<<<(E + 511) / 512, 512>>>(row, E);
    scan_kernel<<<1, 1024>>>();
    fill_kernel<<<(E + 511) / 512, 512>>>(vals, row, col, E);
    gather_split_kernel<<<(N_NODES + 3) / 4, 512>>>(x);
    split_w_kernel<<<256, 256>>>(W);

    dim3 grid(N_OUT / GBN, M_PAD / GBM);   // (4, 157)
    mma_gemm_kernel<<<grid, 256, GEMM_SMEM>>>(out);
}